// round 6
// baseline (speedup 1.0000x reference)
#include <cuda_runtime.h>

// Problem constants
#define BC        20      // B*C
#define HLEN      200     // his_length
#define DK        20
#define NROWS     4000    // BC*HLEN
#define ROW_ELEMS 8000    // D_INNER(400) * DK(20)
#define CTX_ELEMS (NROWS*DK)        // 80000
#define ATTN_OFF  CTX_ELEMS

// Projected q,k,v,c in TRANSPOSED layout: [bc][d][h] -> (bc*20+d)*200+h
__device__ float g_qT[CTX_ELEMS];
__device__ float g_kT[CTX_ELEMS];
__device__ float g_vT[CTX_ELEMS];
__device__ float g_cT[CTX_ELEMS];

// ---------------------------------------------------------------------------
// Kernel 1: projections.  grid = (row 0..3999, tensor 0..2); 200 threads.
// q[r][d] = sum_n X[r][n][d] * W[n] + b   (n=0..399, d=0..19).
// c[r][d] = sum_n cdd[r][n][d] * W1[n] + b1 — folded into a==2.
// Outputs written TRANSPOSED per bc so downstream kernels read coalesced.
// ---------------------------------------------------------------------------
__global__ __launch_bounds__(200) void proj_kernel(
    const float* __restrict__ Q, const float* __restrict__ K,
    const float* __restrict__ V, const float* __restrict__ cdd,
    const float* __restrict__ W, const float* __restrict__ bp,
    const float* __restrict__ W1, const float* __restrict__ b1p)
{
    __shared__ float Ws[400];
    __shared__ float4 red[200];

    const int r = blockIdx.x;      // row 0..3999
    const int a = blockIdx.y;      // tensor 0..2
    const int t = threadIdx.x;     // 0..199
    const int bc = r / HLEN;
    const int h  = r - bc * HLEN;

    Ws[t]       = W[t];
    Ws[t + 200] = W[t + 200];
    __syncthreads();

    const float bias = __ldg(bp);
    const size_t base = (size_t)r * ROW_ELEMS;

    const float* src = (a == 0) ? (Q + base) : (a == 1) ? (K + base) : (V + base);
    float*       dst = (a == 0) ? g_qT : (a == 1) ? g_kT : g_vT;

    const float4* p = (const float4*)src;
    float acc0 = 0.f, acc1 = 0.f, acc2 = 0.f, acc3 = 0.f;
    #pragma unroll
    for (int j = 0; j < 10; j++) {
        const int i4 = t + 200 * j;
        const float4 v4 = p[i4];
        const float w = Ws[(i4 * 4) / 20];     // same n for all 4 lanes
        acc0 += v4.x * w;
        acc1 += v4.y * w;
        acc2 += v4.z * w;
        acc3 += v4.w * w;
    }
    red[t] = make_float4(acc0, acc1, acc2, acc3);
    __syncthreads();

    if (t < 20) {
        // output dim d = t: contributions from threads tp with tp%5 == d/4,
        // accumulator slot e = d%4.
        const int e  = t & 3;
        const int st = t >> 2;
        float s = bias;
        #pragma unroll 8
        for (int tp = st; tp < 200; tp += 5)
            s += ((const float*)&red[tp])[e];
        dst[(bc * DK + t) * HLEN + h] = s;
    }

    // cdd projection: 20x20 per row, thread d does the 20-term reduction.
    if (a == 2 && t < 20) {
        const float b1 = __ldg(b1p);
        const float* cb = cdd + (size_t)r * 400;
        float s = b1;
        #pragma unroll
        for (int n = 0; n < 20; n++)
            s += cb[n * 20 + t] * __ldg(W1 + n);
        g_cT[(bc * DK + t) * HLEN + h] = s;
    }
}

// ---------------------------------------------------------------------------
// Kernel 2 (fused attention).  grid = (bc=20, mt=8); 256 threads; 25 rows.
// smem layout (floats):
//   ys[40*200]  : [k|c]^T cols  (0)
//   xs[40*25]   : [q|k] rows    (8000)
//   vt[20*200]  : v^T           (9000)
//   E [25*200]  : exp(scores)   (13000)
//   ctxp[250*20]: ctx partials  (18000)
//   partials[256], rss[25]      (23000, 23256)
// Thread (m = t/10, ng = t%10) keeps its 40-deep x-row in registers; covers
// n = ng + 10*j (j<20) -> all ys/vt shared reads broadcast/conflict-free.
// Context accumulated with unnormalized e; rescaled by 1/sum at the end.
// ---------------------------------------------------------------------------
#define SMEM_FLOATS 23288
#define SMEM_BYTES  (SMEM_FLOATS * 4)

__global__ __launch_bounds__(256, 1) void attn_fused(float* __restrict__ out)
{
    extern __shared__ float sm[];
    float* ys       = sm;            // 8000
    float* xs       = sm + 8000;     // 1000
    float* vt       = sm + 9000;     // 4000
    float* E        = sm + 13000;    // 5000
    float* ctxp     = sm + 18000;    // 5000
    float* partials = sm + 23000;    // 256
    float* rss      = sm + 23256;    // 25

    const int bc = blockIdx.x;
    const int m0 = blockIdx.y * 25;
    const int t  = threadIdx.x;

    // ---- stage (coalesced LDG from transposed gmem, conflict-free STS) ----
    for (int i = t; i < 8000; i += 256) {
        const int d = i / 200, n = i - 200 * d;
        ys[i] = (d < 20) ? g_kT[(bc * DK + d) * HLEN + n]
                         : g_cT[(bc * DK + d - 20) * HLEN + n];
    }
    for (int i = t; i < 1000; i += 256) {
        const int d = i / 25, m = i - 25 * d;
        xs[i] = (d < 20) ? g_qT[(bc * DK + d) * HLEN + m0 + m]
                         : g_kT[(bc * DK + d - 20) * HLEN + m0 + m];
    }
    for (int i = t; i < 4000; i += 256) {
        const int d = i / 200, n = i - 200 * d;
        vt[i] = g_vT[(bc * DK + d) * HLEN + n];
    }
    if (t >= 250) partials[t] = 0.f;
    __syncthreads();

    const float inv_sqrt_dk = 0.22360679774997896f;   // 1/sqrt(20)

    // ---- scores + exp + unnormalized context ----
    if (t < 250) {
        const int m  = t / 10;
        const int ng = t - 10 * m;

        float xr[40];
        #pragma unroll
        for (int d = 0; d < 40; d++) xr[d] = xs[d * 25 + m];

        float ctxa[DK];
        #pragma unroll
        for (int d = 0; d < DK; d++) ctxa[d] = 0.f;

        float esum = 0.f;
        #pragma unroll
        for (int j = 0; j < 20; j++) {
            const int n = ng + 10 * j;
            float s = 0.f;
            #pragma unroll
            for (int d = 0; d < 40; d++)
                s += xr[d] * ys[d * HLEN + n];
            const float e = __expf(s * inv_sqrt_dk);
            E[m * HLEN + n] = e;
            esum += e;
            #pragma unroll
            for (int d = 0; d < DK; d++)
                ctxa[d] += e * vt[d * HLEN + n];
        }
        partials[t] = esum;
        #pragma unroll
        for (int d = 0; d < DK; d++)
            ctxp[t * DK + d] = ctxa[d];
    }
    __syncthreads();

    // ---- row denominators ----
    if (t < 25) {
        float s = 1e-8f;
        #pragma unroll
        for (int ng = 0; ng < 10; ng++)
            s += partials[t * 10 + ng];
        rss[t] = 1.f / s;
    }
    __syncthreads();

    // ---- normalized attn writes (coalesced, warp per row) ----
    {
        const int w = t >> 5, lane = t & 31;
        for (int m = w; m < 25; m += 8) {
            const float rs = rss[m];
            float* attn = out + ATTN_OFF + (size_t)(bc * HLEN + m0 + m) * HLEN;
            #pragma unroll
            for (int k = 0; k < 7; k++) {
                const int g = lane + 32 * k;
                if (g < HLEN) attn[g] = E[m * HLEN + g] * rs;
            }
        }
    }

    // ---- context reduce + write ----
    for (int idx = t; idx < 25 * DK; idx += 256) {
        const int m = idx / DK, d = idx - DK * m;
        float s = 0.f;
        #pragma unroll
        for (int ng = 0; ng < 10; ng++)
            s += ctxp[(m * 10 + ng) * DK + d];
        out[(bc * HLEN + m0 + m) * DK + d] = s * rss[m];
    }
}

extern "C" void kernel_launch(void* const* d_in, const int* in_sizes, int n_in,
                              void* d_out, int out_size)
{
    const float* Q   = (const float*)d_in[0];
    const float* K   = (const float*)d_in[1];
    const float* V   = (const float*)d_in[2];
    const float* cdd = (const float*)d_in[3];
    const float* W   = (const float*)d_in[4];
    const float* b   = (const float*)d_in[5];
    const float* W1  = (const float*)d_in[6];
    const float* b1  = (const float*)d_in[7];

    cudaFuncSetAttribute(attn_fused,
                         cudaFuncAttributeMaxDynamicSharedMemorySize, SMEM_BYTES);

    proj_kernel<<<dim3(NROWS, 3), 200>>>(Q, K, V, cdd, W, b, W1, b1);
    attn_fused<<<dim3(BC, 8), 256, SMEM_BYTES>>>((float*)d_out);
}

// round 11
// speedup vs baseline: 1.1913x; 1.1913x over previous
#include <cuda_runtime.h>

// Problem constants
#define BC        20      // B*C
#define HLEN      200     // his_length
#define DK        20
#define NROWS     4000    // BC*HLEN
#define ROW_ELEMS 8000    // D_INNER(400) * DK(20)
#define CTX_ELEMS (NROWS*DK)        // 80000
#define ATTN_OFF  CTX_ELEMS

// Projected q,k,v,c in TRANSPOSED layout: [bc][d][h] -> (bc*20+d)*200+h
__device__ float g_qT[CTX_ELEMS];
__device__ float g_kT[CTX_ELEMS];
__device__ float g_vT[CTX_ELEMS];
__device__ float g_cT[CTX_ELEMS];

// ---------------------------------------------------------------------------
// Kernel 1: projections.  grid = (row 0..3999, tensor 0..2); 200 threads.
// q[r][d] = sum_n X[r][n][d] * W[n] + b   (n=0..399, d=0..19).
// c[r][d] = sum_n cdd[r][n][d] * W1[n] + b1 — folded into a==2.
// Outputs written TRANSPOSED per bc so downstream kernels read coalesced.
// (82.8% DRAM in R5 — near roofline; unchanged.)
// ---------------------------------------------------------------------------
__global__ __launch_bounds__(200) void proj_kernel(
    const float* __restrict__ Q, const float* __restrict__ K,
    const float* __restrict__ V, const float* __restrict__ cdd,
    const float* __restrict__ W, const float* __restrict__ bp,
    const float* __restrict__ W1, const float* __restrict__ b1p)
{
    __shared__ float Ws[400];
    __shared__ float4 red[200];

    const int r = blockIdx.x;      // row 0..3999
    const int a = blockIdx.y;      // tensor 0..2
    const int t = threadIdx.x;     // 0..199
    const int bc = r / HLEN;
    const int h  = r - bc * HLEN;

    Ws[t]       = W[t];
    Ws[t + 200] = W[t + 200];
    __syncthreads();

    const float bias = __ldg(bp);
    const size_t base = (size_t)r * ROW_ELEMS;

    const float* src = (a == 0) ? (Q + base) : (a == 1) ? (K + base) : (V + base);
    float*       dst = (a == 0) ? g_qT : (a == 1) ? g_kT : g_vT;

    const float4* p = (const float4*)src;
    float acc0 = 0.f, acc1 = 0.f, acc2 = 0.f, acc3 = 0.f;
    #pragma unroll
    for (int j = 0; j < 10; j++) {
        const int i4 = t + 200 * j;
        const float4 v4 = p[i4];
        const float w = Ws[(i4 * 4) / 20];     // same n for all 4 lanes
        acc0 += v4.x * w;
        acc1 += v4.y * w;
        acc2 += v4.z * w;
        acc3 += v4.w * w;
    }
    red[t] = make_float4(acc0, acc1, acc2, acc3);
    __syncthreads();

    if (t < 20) {
        // output dim d = t: contributions from threads tp with tp%5 == d/4,
        // accumulator slot e = d%4.
        const int e  = t & 3;
        const int st = t >> 2;
        float s = bias;
        #pragma unroll 8
        for (int tp = st; tp < 200; tp += 5)
            s += ((const float*)&red[tp])[e];
        dst[(bc * DK + t) * HLEN + h] = s;
    }

    // cdd projection: 20x20 per row, thread d does the 20-term reduction.
    if (a == 2 && t < 20) {
        const float b1 = __ldg(b1p);
        const float* cb = cdd + (size_t)r * 400;
        float s = b1;
        #pragma unroll
        for (int n = 0; n < 20; n++)
            s += cb[n * 20 + t] * __ldg(W1 + n);
        g_cT[(bc * DK + t) * HLEN + h] = s;
    }
}

// ---------------------------------------------------------------------------
// Kernel 2 (fused attention, v2 fixed).  grid = (bc=20, mt=20); 256 threads;
// block owns 10 rows x full n-range (row sums intra-block).
// Thread (m = t/25, ng = t%25) covers n = ng + 25*j (j<8): e[8] kept in
// registers (no smem E), 40-deep x row in registers, ys/vt reads are
// stride-1-per-lane -> conflict-free LDS.  Context accumulated with
// unnormalized e, rescaled by 1/sum at the end.
// ctxp padded to stride 21 (odd) -> conflict-free partial writes/reads.
// smem (floats): ys=8000, xs=400, vt=4000, partials=256,
//                ctxp=250*21=5250, rss=14 -> 17920 (71.7KB)
// ---------------------------------------------------------------------------
#define CTXP_STR 21
#define SM_YS    0
#define SM_XS    8000
#define SM_VT    8400
#define SM_PART  12400
#define SM_CTXP  12656
#define SM_RSS   (SM_CTXP + 250 * CTXP_STR)   // 17906
#define SMEM_FLOATS 17920
#define SMEM_BYTES  (SMEM_FLOATS * 4)

__global__ __launch_bounds__(256, 2) void attn_fused(float* __restrict__ out)
{
    extern __shared__ float sm[];
    float* ys       = sm + SM_YS;    // [d][n] d<40
    float* xs       = sm + SM_XS;    // [d][m] d<40, m<10
    float* vt       = sm + SM_VT;    // [d][n] d<20
    float* partials = sm + SM_PART;  // 256
    float* ctxp     = sm + SM_CTXP;  // [t][d] t<250, stride 21
    float* rss      = sm + SM_RSS;   // 10

    const int bc = blockIdx.x;
    const int m0 = blockIdx.y * 10;
    const int t  = threadIdx.x;

    // ---- stage (coalesced LDG from transposed gmem, conflict-free STS) ----
    for (int i = t; i < 8000; i += 256) {
        const int d = i / 200, n = i - 200 * d;
        ys[i] = (d < 20) ? g_kT[(bc * DK + d) * HLEN + n]
                         : g_cT[(bc * DK + d - 20) * HLEN + n];
    }
    for (int i = t; i < 4000; i += 256) {
        const int d = i / 200, n = i - 200 * d;
        vt[i] = g_vT[(bc * DK + d) * HLEN + n];
    }
    for (int i = t; i < 400; i += 256) {          // FIX: strided loop (was if(t<400))
        const int d = i / 10, m = i - 10 * d;
        xs[i] = (d < 20) ? g_qT[(bc * DK + d) * HLEN + m0 + m]
                         : g_kT[(bc * DK + d - 20) * HLEN + m0 + m];
    }
    if (t >= 250) partials[t] = 0.f;
    __syncthreads();

    const float inv_sqrt_dk = 0.22360679774997896f;   // 1/sqrt(20)
    float e[8];

    if (t < 250) {
        const int m  = t / 25;
        const int ng = t - 25 * m;

        float xr[40];
        #pragma unroll
        for (int d = 0; d < 40; d++) xr[d] = xs[d * 10 + m];

        float ctxa[DK];
        #pragma unroll
        for (int d = 0; d < DK; d++) ctxa[d] = 0.f;

        float esum = 0.f;
        #pragma unroll
        for (int j = 0; j < 8; j++) {
            const int n = ng + 25 * j;
            float s = 0.f;
            #pragma unroll
            for (int d = 0; d < 40; d++)
                s += xr[d] * ys[d * HLEN + n];
            e[j] = __expf(s * inv_sqrt_dk);
            esum += e[j];
            #pragma unroll
            for (int d = 0; d < DK; d++)
                ctxa[d] += e[j] * vt[d * HLEN + n];
        }
        partials[t] = esum;
        #pragma unroll
        for (int d = 0; d < DK; d++)
            ctxp[t * CTXP_STR + d] = ctxa[d];
    }
    __syncthreads();

    // ---- row denominators (10 rows, 25 partials each) ----
    if (t < 10) {
        float s = 1e-8f;
        #pragma unroll
        for (int g = 0; g < 25; g++)
            s += partials[t * 25 + g];
        rss[t] = 1.f / s;
    }
    __syncthreads();

    // ---- normalized attn writes straight from registers (coalesced) ----
    if (t < 250) {
        const int m  = t / 25;
        const int ng = t - 25 * m;
        const float rs = rss[m];
        float* attn = out + ATTN_OFF + (size_t)(bc * HLEN + m0 + m) * HLEN;
        #pragma unroll
        for (int j = 0; j < 8; j++)
            attn[ng + 25 * j] = e[j] * rs;
    }

    // ---- context reduce + write (200 outputs, 25 partials each) ----
    if (t < 200) {
        const int m = t / DK, d = t - DK * m;
        float s = 0.f;
        #pragma unroll
        for (int g = 0; g < 25; g++)
            s += ctxp[(m * 25 + g) * CTXP_STR + d];
        out[(bc * HLEN + m0 + m) * DK + d] = s * rss[m];
    }
}

extern "C" void kernel_launch(void* const* d_in, const int* in_sizes, int n_in,
                              void* d_out, int out_size)
{
    const float* Q   = (const float*)d_in[0];
    const float* K   = (const float*)d_in[1];
    const float* V   = (const float*)d_in[2];
    const float* cdd = (const float*)d_in[3];
    const float* W   = (const float*)d_in[4];
    const float* b   = (const float*)d_in[5];
    const float* W1  = (const float*)d_in[6];
    const float* b1  = (const float*)d_in[7];

    cudaFuncSetAttribute(attn_fused,
                         cudaFuncAttributeMaxDynamicSharedMemorySize, SMEM_BYTES);

    proj_kernel<<<dim3(NROWS, 3), 200>>>(Q, K, V, cdd, W, b, W1, b1);
    attn_fused<<<dim3(BC, 20), 256, SMEM_BYTES>>>((float*)d_out);
}